// round 11
// baseline (speedup 1.0000x reference)
#include <cuda_runtime.h>
#include <cuda_fp16.h>
#include <cstdint>
#include <cstddef>

// Problem dims: y[b,m,n] = sum_k x[b,m,k] w[k,n]; flatten b,m -> M
#define MDIM 8192
#define KDIM 4096
#define NDIM 4096

// GEMM tiling: CTA 128x128x32, 8 warps (2m x 4n), warp tile 64x32.
// 6 stages, consumed in groups of 2 kts with ONE barrier per group.
#define BM 128
#define BN 128
#define BK 32
#define KT (KDIM / BK)    // 128
#define NGROUP (KT / 2)   // 64
#define THREADS 256

#define LDA 40   // 32 + 8 pad (fp16 elems per A smem row)
#define LDB 136  // 128 + 8 pad
#define A_TILE_B (BM * LDA * 2)        // 10240
#define B_TILE_B (BK * LDB * 2)        // 8704
#define STAGE_B (A_TILE_B + B_TILE_B)  // 18944
#define STAGES 6
#define SMEM_B (STAGES * STAGE_B)      // 113664 -> 2 CTAs/SM (227.3KB)

// fp16 scratch (allocation-free rule: __device__ globals)
__device__ __half g_xh[(size_t)MDIM * KDIM];  // 67 MB
__device__ __half g_wh[(size_t)KDIM * NDIM];  // 33.5 MB

static __device__ __forceinline__ uint32_t smem_u32(const void* p) {
    uint32_t a;
    asm("{ .reg .u64 t; cvta.to.shared.u64 t, %1; cvt.u32.u64 %0, t; }"
        : "=r"(a) : "l"(p));
    return a;
}

#define CP_ASYNC16(dst, src) \
    asm volatile("cp.async.cg.shared.global [%0], [%1], 16;" :: "r"(dst), "l"(src))
#define CP_COMMIT() asm volatile("cp.async.commit_group;" ::: "memory")
#define CP_WAIT(n)  asm volatile("cp.async.wait_group %0;" :: "n"(n) : "memory")

#define LDMATRIX_X4(r0, r1, r2, r3, addr)                                  \
    asm volatile("ldmatrix.sync.aligned.m8n8.x4.shared.b16 "               \
                 "{%0,%1,%2,%3}, [%4];"                                    \
                 : "=r"(r0), "=r"(r1), "=r"(r2), "=r"(r3) : "r"(addr))

#define LDMATRIX_X4_T(r0, r1, r2, r3, addr)                                \
    asm volatile("ldmatrix.sync.aligned.m8n8.x4.trans.shared.b16 "         \
                 "{%0,%1,%2,%3}, [%4];"                                    \
                 : "=r"(r0), "=r"(r1), "=r"(r2), "=r"(r3) : "r"(addr))

#define MMA16816(d, a, b0, b1)                                             \
    asm volatile("mma.sync.aligned.m16n8k16.row.col.f32.f16.f16.f32 "      \
                 "{%0,%1,%2,%3}, {%4,%5,%6,%7}, {%8,%9}, {%0,%1,%2,%3};"   \
                 : "+f"((d)[0]), "+f"((d)[1]), "+f"((d)[2]), "+f"((d)[3])  \
                 : "r"((a)[0]), "r"((a)[1]), "r"((a)[2]), "r"((a)[3]),     \
                   "r"(b0), "r"(b1))

// ---------------------------------------------------------------------------
// prep: fused fp32 -> fp16 for both x and w (one launch)
// ---------------------------------------------------------------------------
#define XCHUNKS ((size_t)MDIM * KDIM / 4)  // 8388608 float4s
#define WCHUNKS ((size_t)KDIM * NDIM / 4)  // 4194304 float4s

__global__ void cvt_both_kernel(const float4* __restrict__ x4,
                                const float4* __restrict__ w4) {
    size_t i = (size_t)blockIdx.x * blockDim.x + threadIdx.x;
    const float4* src;
    uint2* dst;
    if (i < XCHUNKS) {
        src = x4 + i;
        dst = reinterpret_cast<uint2*>(g_xh) + i;
    } else {
        src = w4 + (i - XCHUNKS);
        dst = reinterpret_cast<uint2*>(g_wh) + (i - XCHUNKS);
    }
    float4 v = *src;
    __half2 h0 = __floats2half2_rn(v.x, v.y);
    __half2 h1 = __floats2half2_rn(v.z, v.w);
    uint2 o;
    o.x = *reinterpret_cast<uint32_t*>(&h0);
    o.y = *reinterpret_cast<uint32_t*>(&h1);
    *dst = o;
}

// ---------------------------------------------------------------------------
// GEMM: 2 CTAs/SM; one barrier + one wait per 2-kt group (3 groups buffered)
// ---------------------------------------------------------------------------
__global__ void __launch_bounds__(THREADS, 2) gemm_kernel(float* __restrict__ out) {
    extern __shared__ char smem_raw[];
    const uint32_t smem = smem_u32(smem_raw);

    const int tid = threadIdx.x;
    const int lane = tid & 31;
    const int wid = tid >> 5;
    const int warp_m = wid & 1;   // 0..1
    const int warp_n = wid >> 1;  // 0..3

    const int m0 = blockIdx.y * BM;
    const int n0 = blockIdx.x * BN;

    const __half* gA = g_xh + (size_t)m0 * KDIM;
    const __half* gB = g_wh + n0;

    // ---- cp.async addresses ----
    // A tile: 128 rows x 32 cols -> 512 chunks, 4 chunks/row
    uint32_t sA_dst[2];
    const __half* gA_src[2];
#pragma unroll
    for (int i = 0; i < 2; ++i) {
        int c = tid + i * THREADS;
        int row = c >> 2, ch = c & 3;
        sA_dst[i] = smem + (uint32_t)(row * LDA + ch * 8) * 2;
        gA_src[i] = gA + (size_t)row * KDIM + ch * 8;
    }
    // B tile: 32 rows x 128 cols -> 512 chunks, 16 chunks/row
    uint32_t sB_dst[2];
    const __half* gB_src[2];
#pragma unroll
    for (int i = 0; i < 2; ++i) {
        int c = tid + i * THREADS;
        int row = c >> 4, ch = c & 15;
        sB_dst[i] = smem + A_TILE_B + (uint32_t)(row * LDB + ch * 8) * 2;
        gB_src[i] = gB + (size_t)row * NDIM + ch * 8;
    }

#define ISSUE_KT(slot, kt_)                                                 \
    do {                                                                    \
        const uint32_t sb = (uint32_t)(slot) * STAGE_B;                     \
        const size_t kb = (size_t)(kt_) * BK;                               \
        _Pragma("unroll")                                                   \
        for (int i = 0; i < 2; ++i)                                         \
            CP_ASYNC16(sA_dst[i] + sb, gA_src[i] + kb);                     \
        _Pragma("unroll")                                                   \
        for (int i = 0; i < 2; ++i)                                         \
            CP_ASYNC16(sB_dst[i] + sb, gB_src[i] + kb * NDIM);              \
    } while (0)

    // ---- fragment base addresses ----
    const uint32_t a_frag =
        smem + (uint32_t)((warp_m * 64 + (lane & 15)) * LDA + (lane >> 4) * 8) * 2;
    const uint32_t b_frag =
        smem + A_TILE_B +
        (uint32_t)((lane & 15) * LDB + warp_n * 32 + (lane >> 4) * 8) * 2;

    float acc[4][4][4];
#pragma unroll
    for (int mi = 0; mi < 4; ++mi)
#pragma unroll
        for (int ni = 0; ni < 4; ++ni)
#pragma unroll
            for (int q = 0; q < 4; ++q) acc[mi][ni][q] = 0.f;

    // ---- prologue: 2 groups (4 kts) in flight ----
    ISSUE_KT(0, 0); ISSUE_KT(1, 1); CP_COMMIT();
    ISSUE_KT(2, 2); ISSUE_KT(3, 3); CP_COMMIT();

    // ---- mainloop over 2-kt groups ----
    for (int g = 0; g < NGROUP; ++g) {
        CP_WAIT(1);        // group g's 2 stages resident
        __syncthreads();   // all warps done with group g-1 -> safe to overwrite

        if (g + 2 < NGROUP) {
            const int sb2 = ((g + 2) % 3) * 2;
            ISSUE_KT(sb2, 2 * (g + 2));
            ISSUE_KT(sb2 + 1, 2 * (g + 2) + 1);
        }
        CP_COMMIT();

        const int slot0 = (g % 3) * 2;
#pragma unroll
        for (int half = 0; half < 2; ++half) {
            const uint32_t sb = (uint32_t)(slot0 + half) * STAGE_B;
            const uint32_t aB = a_frag + sb;
            const uint32_t bB = b_frag + sb;
#pragma unroll
            for (int kk = 0; kk < 2; ++kk) {
                uint32_t a[4][4], b[2][4];
#pragma unroll
                for (int mi = 0; mi < 4; ++mi)
                    LDMATRIX_X4(a[mi][0], a[mi][1], a[mi][2], a[mi][3],
                                aB + (uint32_t)(mi * 16 * LDA + kk * 16) * 2);
#pragma unroll
                for (int nj = 0; nj < 2; ++nj)
                    LDMATRIX_X4_T(b[nj][0], b[nj][1], b[nj][2], b[nj][3],
                                  bB + (uint32_t)(kk * 16 * LDB + nj * 16) * 2);
#pragma unroll
                for (int mi = 0; mi < 4; ++mi)
#pragma unroll
                    for (int nj = 0; nj < 2; ++nj) {
                        MMA16816(acc[mi][2 * nj + 0], a[mi], b[nj][0], b[nj][1]);
                        MMA16816(acc[mi][2 * nj + 1], a[mi], b[nj][2], b[nj][3]);
                    }
            }
        }
    }

    // ---- epilogue: direct fp32 stores ----
    const int mg = m0 + warp_m * 64 + (lane >> 2);
    const int ng = n0 + warp_n * 32 + (lane & 3) * 2;
#pragma unroll
    for (int mi = 0; mi < 4; ++mi) {
#pragma unroll
        for (int ni = 0; ni < 4; ++ni) {
            float* p0 = out + (size_t)(mg + mi * 16) * NDIM + ng + ni * 8;
            float* p1 = p0 + 8 * NDIM;
            *reinterpret_cast<float2*>(p0) = make_float2(acc[mi][ni][0], acc[mi][ni][1]);
            *reinterpret_cast<float2*>(p1) = make_float2(acc[mi][ni][2], acc[mi][ni][3]);
        }
    }
}

// ---------------------------------------------------------------------------
extern "C" void kernel_launch(void* const* d_in, const int* in_sizes, int n_in,
                              void* d_out, int out_size) {
    const float* x = (const float*)d_in[0];  // (4, 2048, 4096) fp32
    const float* w = (const float*)d_in[1];  // (4096, 4096) fp32 ternary
    float* out = (float*)d_out;              // (4, 2048, 4096) fp32

    size_t total_chunks = XCHUNKS + WCHUNKS;  // 12582912
    cvt_both_kernel<<<(int)(total_chunks / 256), 256>>>(
        reinterpret_cast<const float4*>(x), reinterpret_cast<const float4*>(w));

    cudaFuncSetAttribute(gemm_kernel, cudaFuncAttributeMaxDynamicSharedMemorySize,
                         SMEM_B);
    dim3 grid(NDIM / BN, MDIM / BM);  // (32, 64)
    gemm_kernel<<<grid, THREADS, SMEM_B>>>(out);
}

// round 12
// speedup vs baseline: 1.6981x; 1.6981x over previous
#include <cuda_runtime.h>
#include <cuda_fp16.h>
#include <cstdint>
#include <cstddef>

// Problem dims: y[b,m,n] = sum_k x[b,m,k] w[k,n]; flatten b,m -> M
#define MDIM 8192
#define KDIM 4096
#define NDIM 4096

// GEMM tiling: CTA 128x128x64, 8 warps (2m x 4n), warp tile 64x32, 3 stages,
// 2 CTAs/SM. Flat 8-unit software pipeline per kt with cross-kt prefetch.
#define BM 128
#define BN 128
#define BK 64
#define STAGES 3
#define KT (KDIM / BK)  // 64
#define THREADS 256

#define LDA 72   // 64 + 8 pad (fp16 elems per A smem row)
#define LDB 136  // 128 + 8 pad
#define A_TILE_B (BM * LDA * 2)        // 18432
#define B_TILE_B (BK * LDB * 2)        // 17408
#define STAGE_B (A_TILE_B + B_TILE_B)  // 35840
#define SMEM_B (STAGES * STAGE_B)      // 107520 -> 2 CTAs/SM

// fp16 scratch (allocation-free rule: __device__ globals)
__device__ __half g_xh[(size_t)MDIM * KDIM];  // 67 MB
__device__ __half g_wh[(size_t)KDIM * NDIM];  // 33.5 MB

static __device__ __forceinline__ uint32_t smem_u32(const void* p) {
    uint32_t a;
    asm("{ .reg .u64 t; cvta.to.shared.u64 t, %1; cvt.u32.u64 %0, t; }"
        : "=r"(a) : "l"(p));
    return a;
}

#define CP_ASYNC16(dst, src) \
    asm volatile("cp.async.cg.shared.global [%0], [%1], 16;" :: "r"(dst), "l"(src))
#define CP_COMMIT() asm volatile("cp.async.commit_group;" ::: "memory")
#define CP_WAIT(n)  asm volatile("cp.async.wait_group %0;" :: "n"(n) : "memory")

#define LDMATRIX_X4(r0, r1, r2, r3, addr)                                  \
    asm volatile("ldmatrix.sync.aligned.m8n8.x4.shared.b16 "               \
                 "{%0,%1,%2,%3}, [%4];"                                    \
                 : "=r"(r0), "=r"(r1), "=r"(r2), "=r"(r3) : "r"(addr))

#define LDMATRIX_X4_T(r0, r1, r2, r3, addr)                                \
    asm volatile("ldmatrix.sync.aligned.m8n8.x4.trans.shared.b16 "         \
                 "{%0,%1,%2,%3}, [%4];"                                    \
                 : "=r"(r0), "=r"(r1), "=r"(r2), "=r"(r3) : "r"(addr))

#define MMA16816(d, a, b0, b1)                                             \
    asm volatile("mma.sync.aligned.m16n8k16.row.col.f32.f16.f16.f32 "      \
                 "{%0,%1,%2,%3}, {%4,%5,%6,%7}, {%8,%9}, {%0,%1,%2,%3};"   \
                 : "+f"((d)[0]), "+f"((d)[1]), "+f"((d)[2]), "+f"((d)[3])  \
                 : "r"((a)[0]), "r"((a)[1]), "r"((a)[2]), "r"((a)[3]),     \
                   "r"(b0), "r"(b1))

// ---------------------------------------------------------------------------
// prep: fused fp32 -> fp16 for both x and w (one launch)
// ---------------------------------------------------------------------------
#define XCHUNKS ((size_t)MDIM * KDIM / 4)  // 8388608 float4s
#define WCHUNKS ((size_t)KDIM * NDIM / 4)  // 4194304 float4s

__global__ void cvt_both_kernel(const float4* __restrict__ x4,
                                const float4* __restrict__ w4) {
    size_t i = (size_t)blockIdx.x * blockDim.x + threadIdx.x;
    const float4* src;
    uint2* dst;
    if (i < XCHUNKS) {
        src = x4 + i;
        dst = reinterpret_cast<uint2*>(g_xh) + i;
    } else {
        src = w4 + (i - XCHUNKS);
        dst = reinterpret_cast<uint2*>(g_wh) + (i - XCHUNKS);
    }
    float4 v = *src;
    __half2 h0 = __floats2half2_rn(v.x, v.y);
    __half2 h1 = __floats2half2_rn(v.z, v.w);
    uint2 o;
    o.x = *reinterpret_cast<uint32_t*>(&h0);
    o.y = *reinterpret_cast<uint32_t*>(&h1);
    *dst = o;
}

// ---------------------------------------------------------------------------
// GEMM
// ---------------------------------------------------------------------------
__global__ void __launch_bounds__(THREADS, 2) gemm_kernel(float* __restrict__ out) {
    extern __shared__ char smem_raw[];
    const uint32_t smem = smem_u32(smem_raw);

    const int tid = threadIdx.x;
    const int lane = tid & 31;
    const int wid = tid >> 5;
    const int warp_m = wid & 1;   // 0..1
    const int warp_n = wid >> 1;  // 0..3

    const int m0 = blockIdx.y * BM;
    const int n0 = blockIdx.x * BN;

    // ---- cp.async bases (compile-time increments between the 4 chunks) ----
    // A tile: 128 rows x 64 halfs -> 1024 chunks of 16B, 4/thread (rows +32*i)
    const int rA = tid >> 3, chA = tid & 7;
    const uint32_t sA0 = smem + (uint32_t)(rA * LDA + chA * 8) * 2;
    const __half* gA0 = g_xh + (size_t)(m0 + rA) * KDIM + chA * 8;
    // B tile: 64 rows x 128 halfs -> 1024 chunks, 4/thread (rows +16*i)
    const int rB = tid >> 4, chB = tid & 15;
    const uint32_t sB0 = smem + A_TILE_B + (uint32_t)(rB * LDB + chB * 8) * 2;
    const __half* gB0 = g_wh + (size_t)rB * NDIM + n0 + chB * 8;

#define ISSUE_KT(slot, kt_)                                                  \
    do {                                                                     \
        const uint32_t sb = (uint32_t)(slot) * STAGE_B;                      \
        const size_t kb = (size_t)(kt_) * BK;                                \
        _Pragma("unroll")                                                    \
        for (int i = 0; i < 4; ++i)                                          \
            CP_ASYNC16(sA0 + sb + (uint32_t)(i * 32 * LDA * 2),              \
                       gA0 + (size_t)i * 32 * KDIM + kb);                    \
        _Pragma("unroll")                                                    \
        for (int i = 0; i < 4; ++i)                                          \
            CP_ASYNC16(sB0 + sb + (uint32_t)(i * 16 * LDB * 2),              \
                       gB0 + ((size_t)i * 16 + kb) * NDIM);                  \
    } while (0)

    // ---- fragment base addresses ----
    const uint32_t a_frag =
        smem + (uint32_t)((warp_m * 64 + (lane & 15)) * LDA + (lane >> 4) * 8) * 2;
    const uint32_t b_frag =
        smem + A_TILE_B +
        (uint32_t)((lane & 15) * LDB + warp_n * 32 + (lane >> 4) * 8) * 2;

    // fragment double buffers: a_f[parity][j], b_f[kk&1][nj]
    uint32_t a_f[2][2][4], b_f[2][2][4];

#define LOAD_A_HALF(ab, base, h, kk)                                         \
    do {                                                                     \
        _Pragma("unroll")                                                    \
        for (int j = 0; j < 2; ++j)                                          \
            LDMATRIX_X4(a_f[ab][j][0], a_f[ab][j][1], a_f[ab][j][2],         \
                        a_f[ab][j][3],                                       \
                        (base) + (uint32_t)((((h) * 2 + j) * 16) * LDA +     \
                                            (kk) * 16) * 2);                 \
    } while (0)

#define LOAD_B_KK(bb, base, kk)                                              \
    do {                                                                     \
        _Pragma("unroll")                                                    \
        for (int nj = 0; nj < 2; ++nj)                                       \
            LDMATRIX_X4_T(b_f[bb][nj][0], b_f[bb][nj][1], b_f[bb][nj][2],    \
                          b_f[bb][nj][3],                                    \
                          (base) + (uint32_t)((kk) * 16 * LDB + nj * 16) * 2);\
    } while (0)

    float acc[4][4][4];
#pragma unroll
    for (int mi = 0; mi < 4; ++mi)
#pragma unroll
        for (int ni = 0; ni < 4; ++ni)
#pragma unroll
            for (int q = 0; q < 4; ++q) acc[mi][ni][q] = 0.f;

    // ---- prologue: fill all 3 stages, wait so slots 0 and 1 are complete ----
    ISSUE_KT(0, 0); CP_COMMIT();
    ISSUE_KT(1, 1); CP_COMMIT();
    ISSUE_KT(2, 2); CP_COMMIT();
    CP_WAIT(1);          // slots 0,1 complete (slot 2 may be in flight)
    __syncthreads();     // their data visible to all threads

    // preload unit 0 of kt 0 (a-half 0 of kk0 + b of kk0)
    LOAD_A_HALF(0, a_frag, 0, 0);
    LOAD_B_KK(0, b_frag, 0);

    // ---- mainloop ----
    for (int kt = 0; kt < KT; ++kt) {
        const uint32_t sb  = (uint32_t)(kt % 3) * STAGE_B;
        const uint32_t sbn = (uint32_t)((kt + 1) % 3) * STAGE_B;
        const uint32_t aB  = a_frag + sb,  bB  = b_frag + sb;
        const uint32_t aBn = a_frag + sbn, bBn = b_frag + sbn;

#pragma unroll
        for (int u = 0; u < 8; ++u) {
            // ---- load fragments for unit u+1 (cross-kt at u==7) ----
            if (u < 7) {
                const int un = u + 1, kkn = un >> 1, hn = un & 1;
                LOAD_A_HALF(un & 1, aB, hn, kkn);
                if (hn == 0) LOAD_B_KK(kkn & 1, bB, kkn);
            } else if (kt + 1 < KT) {
                LOAD_A_HALF(0, aBn, 0, 0);
                LOAD_B_KK(0, bBn, 0);
            }
            // ---- MMAs for unit u ----
            const int kk = u >> 1, h = u & 1, ab = u & 1, bb = kk & 1;
#pragma unroll
            for (int j = 0; j < 2; ++j) {
                const int mi = h * 2 + j;
#pragma unroll
                for (int nj = 0; nj < 2; ++nj) {
                    MMA16816(acc[mi][2 * nj + 0], a_f[ab][j],
                             b_f[bb][nj][0], b_f[bb][nj][1]);
                    MMA16816(acc[mi][2 * nj + 1], a_f[ab][j],
                             b_f[bb][nj][2], b_f[bb][nj][3]);
                }
            }
        }

        // ---- stage rotation: sync (units done) -> overwrite -> wait -> sync
        __syncthreads();                       // everyone done reading slot kt
        if (kt + 3 < KT) ISSUE_KT(kt % 3, kt + 3);
        CP_COMMIT();
        CP_WAIT(1);                            // slot kt+2 complete
        __syncthreads();                       // ...and visible to all
    }

    // ---- epilogue: direct fp32 stores ----
    const int mg = m0 + warp_m * 64 + (lane >> 2);
    const int ng = n0 + warp_n * 32 + (lane & 3) * 2;
#pragma unroll
    for (int mi = 0; mi < 4; ++mi) {
#pragma unroll
        for (int ni = 0; ni < 4; ++ni) {
            float* p0 = out + (size_t)(mg + mi * 16) * NDIM + ng + ni * 8;
            float* p1 = p0 + 8 * NDIM;
            *reinterpret_cast<float2*>(p0) = make_float2(acc[mi][ni][0], acc[mi][ni][1]);
            *reinterpret_cast<float2*>(p1) = make_float2(acc[mi][ni][2], acc[mi][ni][3]);
        }
    }
}

// ---------------------------------------------------------------------------
extern "C" void kernel_launch(void* const* d_in, const int* in_sizes, int n_in,
                              void* d_out, int out_size) {
    const float* x = (const float*)d_in[0];  // (4, 2048, 4096) fp32
    const float* w = (const float*)d_in[1];  // (4096, 4096) fp32 ternary
    float* out = (float*)d_out;              // (4, 2048, 4096) fp32

    size_t total_chunks = XCHUNKS + WCHUNKS;  // 12582912
    cvt_both_kernel<<<(int)(total_chunks / 256), 256>>>(
        reinterpret_cast<const float4*>(x), reinterpret_cast<const float4*>(w));

    cudaFuncSetAttribute(gemm_kernel, cudaFuncAttributeMaxDynamicSharedMemorySize,
                         SMEM_B);
    dim3 grid(NDIM / BN, MDIM / BM);  // (32, 64)
    gemm_kernel<<<grid, THREADS, SMEM_B>>>(out);
}